// round 16
// baseline (speedup 1.0000x reference)
#include <cuda_runtime.h>
#include <cuda_fp16.h>
#include <math.h>
#include <cstdint>

// ---------------- problem constants ----------------
#define N_NODES 50000
#define N_EDGES 600000
#define N_PRED  200000
#define ETOT    (N_EDGES + N_NODES)
#define W1      512
#define W2      256
#define H1      4
#define H2      2
#define K1      128
#define K2      512
#define BN_EPS  1e-5f
#define NCHUNK  4

// ---------------- scratch (device globals) ----------------
__device__ __half g_xl1h[(size_t)N_NODES * W1];
__device__ __half g_xr1h[(size_t)N_NODES * W1];
__device__ __half g_xl2h[(size_t)N_NODES * W2];
__device__ __half g_xr2h[(size_t)N_NODES * W2];
__device__ __half g_zh [(size_t)N_NODES * W2];

__device__ __half g_As1[(size_t)N_NODES * K1];
__device__ __half g_As2[(size_t)N_NODES * K2];
__device__ __half g_Wc1[(2 * W1) * K1];
__device__ __half g_Wc2[(2 * W2) * K2];

__device__ float g_bc1[2 * W1];
__device__ float g_bc2[2 * W2];

__device__ int g_deg[N_NODES];
__device__ int g_off[N_NODES + 1];
__device__ int g_cursor[N_NODES];
__device__ int g_csr_src[ETOT];

__device__ float g_bns1[W1];
__device__ float g_bnt1[W1];
__device__ float g_bns2[W2];
__device__ float g_bnt2[W2];

// ---------------- helpers ----------------
__device__ __forceinline__ uint32_t smem_to_u32(const void* p) {
    uint32_t a;
    asm("{ .reg .u64 t; cvta.to.shared.u64 t, %1; cvt.u32.u64 %0, t; }" : "=r"(a) : "l"(p));
    return a;
}
#define SWZ128(b) ((b) ^ (((b) >> 3) & 0x70))

__device__ __forceinline__ void ldmatrix_x4(uint32_t* r, uint32_t addr) {
    asm volatile("ldmatrix.sync.aligned.m8n8.x4.shared.b16 {%0,%1,%2,%3}, [%4];"
                 : "=r"(r[0]), "=r"(r[1]), "=r"(r[2]), "=r"(r[3]) : "r"(addr));
}
__device__ __forceinline__ void mma16816h(float* c, const uint32_t* a,
                                          uint32_t b0, uint32_t b1) {
    asm volatile("mma.sync.aligned.m16n8k16.row.col.f32.f16.f16.f32 "
                 "{%0,%1,%2,%3}, {%4,%5,%6,%7}, {%8,%9}, {%0,%1,%2,%3};"
                 : "+f"(c[0]), "+f"(c[1]), "+f"(c[2]), "+f"(c[3])
                 : "r"(a[0]), "r"(a[1]), "r"(a[2]), "r"(a[3]), "r"(b0), "r"(b1));
}
__device__ __forceinline__ float4 h4_to_f4(uint2 u) {
    float2 lo = __half22float2(*(__half2*)&u.x);
    float2 hi = __half22float2(*(__half2*)&u.y);
    return make_float4(lo.x, lo.y, hi.x, hi.y);
}

// ---------------- prep kernels ----------------
__global__ void cvt_A(const float* __restrict__ X, __half* __restrict__ out, int n) {
    int idx = blockIdx.x * blockDim.x + threadIdx.x;
    if (idx < n) out[idx] = __float2half(X[idx]);
}

__global__ void cvt_W_pair(const float* __restrict__ Wl, const float* __restrict__ Wr,
                           __half* __restrict__ out, int K, int Nn) {
    int idx = blockIdx.x * blockDim.x + threadIdx.x;
    if (idx >= 2 * K * Nn) return;
    const float* W = (idx < K * Nn) ? Wl : Wr;
    int rem = (idx < K * Nn) ? idx : idx - K * Nn;
    int noff = (idx < K * Nn) ? 0 : Nn;
    int k = rem / Nn, n = rem - k * Nn;
    out[(size_t)(n + noff) * K + k] = __float2half(W[rem]);
}

__global__ void cat2(const float* __restrict__ a, const float* __restrict__ b,
                     float* __restrict__ o, int n) {
    int i = blockIdx.x * blockDim.x + threadIdx.x;
    if (i < n) { o[i] = a[i]; o[n + i] = b[i]; }
}

// ---------------- HMMA fp16 GEMM ----------------
#define STAGE_BYTES 32768   // 16KB A + 16KB B

__global__ __launch_bounds__(256, 2)
void gemm_mma(const __half* __restrict__ A, const __half* __restrict__ B,
              const float* __restrict__ bias, __half* __restrict__ Cl,
              __half* __restrict__ Cr,
              int M, int Ks, int Nn, int Wn, int moff) {
    extern __shared__ __align__(1024) char sm[];
    int tid = threadIdx.x;
    int wid = tid >> 5, lane = tid & 31;
    int m0 = (blockIdx.y + moff) * 128, n0 = blockIdx.x * 128;
    int wm = wid >> 1, wn = wid & 1;
    uint32_t smb = smem_to_u32(sm);

    float acc[2][8][4];
#pragma unroll
    for (int t = 0; t < 2; t++)
#pragma unroll
        for (int j = 0; j < 8; j++)
#pragma unroll
            for (int q = 0; q < 4; q++) acc[t][j][q] = 0.f;

    int nch = Ks / 64;

    auto issue_load = [&](int c, int s) {
        uint32_t base = smb + s * STAGE_BYTES;
#pragma unroll
        for (int r = 0; r < 4; r++) {
            int idx = tid + r * 256;
            int row = idx >> 3, j = idx & 7;
            const __half* gp = A + (size_t)(m0 + row) * Ks + c * 64 + j * 8;
            uint32_t sa = base + SWZ128(row * 128 + j * 16);
            int sz = (m0 + row < M) ? 16 : 0;
            asm volatile("cp.async.cg.shared.global [%0], [%1], 16, %2;"
                         :: "r"(sa), "l"(gp), "r"(sz));
        }
#pragma unroll
        for (int r = 0; r < 4; r++) {
            int idx = tid + r * 256;
            int row = idx >> 3, j = idx & 7;
            const __half* gp = B + (size_t)(n0 + row) * Ks + c * 64 + j * 8;
            uint32_t sa = base + 16384 + SWZ128(row * 128 + j * 16);
            asm volatile("cp.async.cg.shared.global [%0], [%1], 16;"
                         :: "r"(sa), "l"(gp));
        }
        asm volatile("cp.async.commit_group;");
    };

    issue_load(0, 0);
    if (nch > 1) issue_load(1, 1);

    for (int c = 0; c < nch; c++) {
        if (c + 1 < nch) asm volatile("cp.async.wait_group 1;");
        else             asm volatile("cp.async.wait_group 0;");
        __syncthreads();
        if (c + 2 < nch) issue_load(c + 2, (c + 2) % 3);

        uint32_t ab = smb + (c % 3) * STAGE_BYTES;
        uint32_t bb = ab + 16384;
#pragma unroll
        for (int kk = 0; kk < 4; kk++) {
            uint32_t af[2][4];
#pragma unroll
            for (int t = 0; t < 2; t++) {
                int rl = 32 * wm + 16 * t + (lane & 15);
                uint32_t ad = ab + SWZ128(rl * 128 + kk * 32 + (lane >> 4) * 16);
                ldmatrix_x4(af[t], ad);
            }
            uint32_t bf[4][4];
#pragma unroll
            for (int p = 0; p < 4; p++) {
                int nl = 64 * wn + 16 * p + ((lane >> 4) << 3) + (lane & 7);
                uint32_t bd = bb + SWZ128(nl * 128 + kk * 32 + ((lane >> 3) & 1) * 16);
                ldmatrix_x4(bf[p], bd);
            }
#pragma unroll
            for (int t = 0; t < 2; t++)
#pragma unroll
                for (int j = 0; j < 8; j++)
                    mma16816h(acc[t][j], af[t],
                              bf[j >> 1][(j & 1) * 2], bf[j >> 1][(j & 1) * 2 + 1]);
        }
    }

    int cbase = n0 + 64 * wn;
    bool isL = (cbase < Wn);
    int coff = isL ? cbase : cbase - Wn;
    __half* Cd = isL ? Cl : Cr;
#pragma unroll
    for (int t = 0; t < 2; t++) {
        int gr = m0 + 32 * wm + 16 * t + (lane >> 2);
#pragma unroll
        for (int j = 0; j < 8; j++) {
            int gc = coff + 8 * j + (lane & 3) * 2;
            float2 bi = *(const float2*)(bias + cbase + 8 * j + (lane & 3) * 2);
            if (gr < M)
                *(__half2*)(Cd + (size_t)gr * Wn + gc) =
                    __floats2half2_rn(acc[t][j][0] + bi.x, acc[t][j][1] + bi.y);
            if (gr + 8 < M)
                *(__half2*)(Cd + (size_t)(gr + 8) * Wn + gc) =
                    __floats2half2_rn(acc[t][j][2] + bi.x, acc[t][j][3] + bi.y);
        }
    }
}

// ---------------- BN prep ----------------
__global__ void bn_prep(const float* __restrict__ bias, const float* __restrict__ g,
                        const float* __restrict__ b, const float* __restrict__ m,
                        const float* __restrict__ v, float* __restrict__ s,
                        float* __restrict__ t, int n) {
    int i = blockIdx.x * blockDim.x + threadIdx.x;
    if (i < n) {
        float sc = g[i] * rsqrtf(v[i] + BN_EPS);
        s[i] = sc;
        t[i] = b[i] + (bias[i] - m[i]) * sc;
    }
}

// ---------------- CSR build ----------------
__global__ void deg_zero(int* deg) {
    int i = blockIdx.x * blockDim.x + threadIdx.x;
    if (i < N_NODES) deg[i] = 0;
}
__global__ void deg_hist(const int* __restrict__ ei, int* __restrict__ deg) {
    int i = blockIdx.x * blockDim.x + threadIdx.x;
    if (i >= ETOT) return;
    int dst = (i < N_EDGES) ? ei[N_EDGES + i] : (i - N_EDGES);
    atomicAdd(&deg[dst], 1);
}
__global__ void scan_kernel(const int* __restrict__ deg, int* __restrict__ off,
                            int* __restrict__ cursor) {
    __shared__ int warp_sums[32];
    const int T = 1024;
    int tid = threadIdx.x;
    int chunk = (N_NODES + T - 1) / T;
    int start = tid * chunk;
    int end = min(start + chunk, N_NODES);
    int local = 0;
    for (int i = start; i < end; i++) local += deg[i];
    int lane = tid & 31, wid = tid >> 5;
    int v = local;
#pragma unroll
    for (int o = 1; o < 32; o <<= 1) {
        int u = __shfl_up_sync(0xFFFFFFFFu, v, o);
        if (lane >= o) v += u;
    }
    if (lane == 31) warp_sums[wid] = v;
    __syncthreads();
    if (wid == 0) {
        int s = warp_sums[lane];
#pragma unroll
        for (int o = 1; o < 32; o <<= 1) {
            int u = __shfl_up_sync(0xFFFFFFFFu, s, o);
            if (lane >= o) s += u;
        }
        warp_sums[lane] = s;
    }
    __syncthreads();
    int excl = v - local + (wid > 0 ? warp_sums[wid - 1] : 0);
    int run = excl;
    for (int i = start; i < end; i++) {
        off[i] = run;
        cursor[i] = run;
        run += deg[i];
    }
    if (tid == T - 1) off[N_NODES] = run;
}
__global__ void csr_scatter(const int* __restrict__ ei, int* __restrict__ cursor,
                            int* __restrict__ csr_src) {
    int i = blockIdx.x * blockDim.x + threadIdx.x;
    if (i >= ETOT) return;
    int src, dst;
    if (i < N_EDGES) { src = ei[i]; dst = ei[N_EDGES + i]; }
    else             { src = dst = i - N_EDGES; }
    int pos = atomicAdd(&cursor[dst], 1);
    csr_src[pos] = src;
}

// ---------------- fused GATv2 aggregation, batch-2 online softmax --------------
// HTOT heads total per node; HP heads handled per warp. 2 warps per node.
// Each warp owns a contiguous HP*128-column slice; math identical per head.
template<int HTOT, int HP>
__global__ __launch_bounds__(256)
void fused_agg(const __half* __restrict__ xl, const __half* __restrict__ xr,
               const float* __restrict__ att,
               const int* __restrict__ off, const int* __restrict__ csr_src,
               const float* __restrict__ bns, const float* __restrict__ bnt,
               __half* __restrict__ outp, int node0, int node1) {
    const int GRPS = HTOT / HP;
    int gw = (blockIdx.x * blockDim.x + threadIdx.x) >> 5;
    int lane = threadIdx.x & 31;
    int node = node0 + gw / GRPS;
    int grp = gw % GRPS;
    if (node >= node1) return;
    const int Wd = HTOT * 128;
    const int cb0 = grp * HP * 128;   // column slice base

    const uint2* xr4 = (const uint2*)(xr + (size_t)node * Wd + cb0);
    const float4* at4 = (const float4*)(att + cb0);

    float4 xrr[HP], attr[HP], acc[HP];
    float m[HP], sum[HP];
#pragma unroll
    for (int h = 0; h < HP; h++) {
        xrr[h]  = h4_to_f4(xr4[h * 32 + lane]);
        attr[h] = at4[h * 32 + lane];
        acc[h]  = make_float4(0.f, 0.f, 0.f, 0.f);
        m[h]    = -INFINITY;
        sum[h]  = 0.f;
    }

    auto loadrow = [&](int src, float4* v) {
        const uint2* p = (const uint2*)(xl + (size_t)src * Wd + cb0);
#pragma unroll
        for (int h = 0; h < HP; h++) v[h] = h4_to_f4(p[h * 32 + lane]);
    };

    int e0 = off[node], e1 = off[node + 1];
    for (int e = e0; e < e1; e += 2) {
        int nb = e1 - e;
        int s0 = csr_src[e];
        int s1 = (nb > 1) ? csr_src[e + 1] : s0;

        float4 v0[HP], v1[HP];
        loadrow(s0, v0);
        loadrow(s1, v1);

        float sc0[HP], sc1[HP];
#pragma unroll
        for (int h = 0; h < HP; h++) {
            float ex = v0[h].x + xrr[h].x; ex = ex > 0.f ? ex : 0.2f * ex;
            float ey = v0[h].y + xrr[h].y; ey = ey > 0.f ? ey : 0.2f * ey;
            float ez = v0[h].z + xrr[h].z; ez = ez > 0.f ? ez : 0.2f * ez;
            float ew = v0[h].w + xrr[h].w; ew = ew > 0.f ? ew : 0.2f * ew;
            sc0[h] = ex * attr[h].x + ey * attr[h].y + ez * attr[h].z + ew * attr[h].w;
            ex = v1[h].x + xrr[h].x; ex = ex > 0.f ? ex : 0.2f * ex;
            ey = v1[h].y + xrr[h].y; ey = ey > 0.f ? ey : 0.2f * ey;
            ez = v1[h].z + xrr[h].z; ez = ez > 0.f ? ez : 0.2f * ez;
            ew = v1[h].w + xrr[h].w; ew = ew > 0.f ? ew : 0.2f * ew;
            sc1[h] = ex * attr[h].x + ey * attr[h].y + ez * attr[h].z + ew * attr[h].w;
        }
#pragma unroll
        for (int o = 16; o > 0; o >>= 1)
#pragma unroll
            for (int h = 0; h < HP; h++) {
                sc0[h] += __shfl_xor_sync(0xFFFFFFFFu, sc0[h], o);
                sc1[h] += __shfl_xor_sync(0xFFFFFFFFu, sc1[h], o);
            }
        if (nb < 2)
#pragma unroll
            for (int h = 0; h < HP; h++) sc1[h] = -INFINITY;

#pragma unroll
        for (int h = 0; h < HP; h++) {
            float sb = fmaxf(sc0[h], sc1[h]);
            float mn = fmaxf(m[h], sb);
            float c  = __expf(m[h] - mn);
            float p0 = __expf(sc0[h] - mn);
            float p1 = __expf(sc1[h] - mn);
            sum[h] = sum[h] * c + p0 + p1;
            acc[h].x = acc[h].x * c + p0 * v0[h].x + p1 * v1[h].x;
            acc[h].y = acc[h].y * c + p0 * v0[h].y + p1 * v1[h].y;
            acc[h].z = acc[h].z * c + p0 * v0[h].z + p1 * v1[h].z;
            acc[h].w = acc[h].w * c + p0 * v0[h].w + p1 * v1[h].w;
            m[h] = mn;
        }
    }

#pragma unroll
    for (int h = 0; h < HP; h++) {
        int cbase = cb0 + h * 128 + lane * 4;
        float4 sc4 = *(const float4*)(bns + cbase);
        float4 tt = *(const float4*)(bnt + cbase);
        float inv = 1.f / sum[h];
        float4 o;
        o.x = fmaxf(fmaf(acc[h].x * inv, sc4.x, tt.x), 0.f);
        o.y = fmaxf(fmaf(acc[h].y * inv, sc4.y, tt.y), 0.f);
        o.z = fmaxf(fmaf(acc[h].z * inv, sc4.z, tt.z), 0.f);
        o.w = fmaxf(fmaf(acc[h].w * inv, sc4.w, tt.w), 0.f);
        __half2 ha = __floats2half2_rn(o.x, o.y);
        __half2 hb = __floats2half2_rn(o.z, o.w);
        uint2 pk;
        pk.x = *(uint32_t*)&ha;
        pk.y = *(uint32_t*)&hb;
        *(uint2*)(outp + (size_t)node * Wd + cbase) = pk;
    }
}

// ---------------- prediction head (fp16 z gather) ----------------
__global__ void head_kernel(const __half* __restrict__ z, const int* __restrict__ pe,
                            const float* __restrict__ pr, const float* __restrict__ pert,
                            const float* __restrict__ Wp, const float* __restrict__ bp,
                            float* __restrict__ out) {
    __shared__ float sw[(W2 * 2 + 3) * 2];
    for (int i = threadIdx.x; i < (W2 * 2 + 3) * 2; i += blockDim.x) sw[i] = Wp[i];
    __syncthreads();

    int w = (blockIdx.x * blockDim.x + threadIdx.x) >> 5;
    int lane = threadIdx.x & 31;
    if (w >= N_PRED) return;
    int s = pe[w], d = pe[N_PRED + w];
    const uint2* zs = (const uint2*)(z + (size_t)s * W2);
    const uint2* zd = (const uint2*)(z + (size_t)d * W2);

    float a0 = 0.f, a1 = 0.f;
#pragma unroll
    for (int q = 0; q < 2; q++) {
        int r = lane * 2 + q;
        float4 vz = h4_to_f4(zs[r]);
        int base = (r * 4) * 2;
        a0 += vz.x * sw[base] + vz.y * sw[base + 2] + vz.z * sw[base + 4] + vz.w * sw[base + 6];
        a1 += vz.x * sw[base + 1] + vz.y * sw[base + 3] + vz.z * sw[base + 5] + vz.w * sw[base + 7];
        float4 vd = h4_to_f4(zd[r]);
        int base2 = (W2 + r * 4) * 2;
        a0 += vd.x * sw[base2] + vd.y * sw[base2 + 2] + vd.z * sw[base2 + 4] + vd.w * sw[base2 + 6];
        a1 += vd.x * sw[base2 + 1] + vd.y * sw[base2 + 3] + vd.z * sw[base2 + 5] + vd.w * sw[base2 + 7];
    }
    if (lane == 0) {
        float prs = pr[s], prd = pr[d], pp = pert[s] * pert[d];
        int b0 = (2 * W2) * 2;
        a0 += prs * sw[b0] + prd * sw[b0 + 2] + pp * sw[b0 + 4];
        a1 += prs * sw[b0 + 1] + prd * sw[b0 + 3] + pp * sw[b0 + 5];
    }
#pragma unroll
    for (int o = 16; o > 0; o >>= 1) {
        a0 += __shfl_xor_sync(0xFFFFFFFFu, a0, o);
        a1 += __shfl_xor_sync(0xFFFFFFFFu, a1, o);
    }
    if (lane == 0) {
        out[(size_t)w * 2 + 0] = a0 + bp[0];
        out[(size_t)w * 2 + 1] = a1 + bp[1];
    }
}

// ---------------- launch ----------------
extern "C" void kernel_launch(void* const* d_in, const int* in_sizes, int n_in,
                              void* d_out, int out_size) {
    const float* x     = (const float*)d_in[0];
    const int*   ei    = (const int*)d_in[1];
    const int*   pe    = (const int*)d_in[2];
    const float* pert  = (const float*)d_in[3];
    const float* pr    = (const float*)d_in[4];
    const float* Wl1   = (const float*)d_in[5];
    const float* bl1   = (const float*)d_in[6];
    const float* Wr1   = (const float*)d_in[7];
    const float* br1   = (const float*)d_in[8];
    const float* att1  = (const float*)d_in[9];
    const float* bias1 = (const float*)d_in[10];
    const float* bn1g  = (const float*)d_in[11];
    const float* bn1b  = (const float*)d_in[12];
    const float* bn1m  = (const float*)d_in[13];
    const float* bn1v  = (const float*)d_in[14];
    const float* Wl2   = (const float*)d_in[15];
    const float* bl2   = (const float*)d_in[16];
    const float* Wr2   = (const float*)d_in[17];
    const float* br2   = (const float*)d_in[18];
    const float* att2  = (const float*)d_in[19];
    const float* bias2 = (const float*)d_in[20];
    const float* bn2g  = (const float*)d_in[21];
    const float* bn2b  = (const float*)d_in[22];
    const float* bn2m  = (const float*)d_in[23];
    const float* bn2v  = (const float*)d_in[24];
    const float* Wp    = (const float*)d_in[25];
    const float* bp    = (const float*)d_in[26];
    float* out = (float*)d_out;

    __half *xl1h, *xr1h, *xl2h, *xr2h, *zh, *As1, *As2, *Wc1, *Wc2;
    float *bc1, *bc2, *bns1, *bnt1, *bns2, *bnt2;
    int *deg, *off, *cursor, *csr_src;
    cudaGetSymbolAddress((void**)&xl1h, g_xl1h);
    cudaGetSymbolAddress((void**)&xr1h, g_xr1h);
    cudaGetSymbolAddress((void**)&xl2h, g_xl2h);
    cudaGetSymbolAddress((void**)&xr2h, g_xr2h);
    cudaGetSymbolAddress((void**)&zh,  g_zh);
    cudaGetSymbolAddress((void**)&bc1, g_bc1);
    cudaGetSymbolAddress((void**)&bc2, g_bc2);
    cudaGetSymbolAddress((void**)&bns1, g_bns1);
    cudaGetSymbolAddress((void**)&bnt1, g_bnt1);
    cudaGetSymbolAddress((void**)&bns2, g_bns2);
    cudaGetSymbolAddress((void**)&bnt2, g_bnt2);
    cudaGetSymbolAddress((void**)&deg, g_deg);
    cudaGetSymbolAddress((void**)&off, g_off);
    cudaGetSymbolAddress((void**)&cursor, g_cursor);
    cudaGetSymbolAddress((void**)&csr_src, g_csr_src);
    cudaGetSymbolAddress((void**)&As1, g_As1);
    cudaGetSymbolAddress((void**)&As2, g_As2);
    cudaGetSymbolAddress((void**)&Wc1, g_Wc1);
    cudaGetSymbolAddress((void**)&Wc2, g_Wc2);

    static int s_init = 0;
    static cudaStream_t s_side;
    static cudaEvent_t s_evF, s_evJ, s_evA[NCHUNK], s_evG;
    if (!s_init) {
        cudaFuncSetAttribute(gemm_mma, cudaFuncAttributeMaxDynamicSharedMemorySize,
                             3 * STAGE_BYTES);
        cudaStreamCreateWithFlags(&s_side, cudaStreamNonBlocking);
        cudaEventCreateWithFlags(&s_evF, cudaEventDisableTiming);
        cudaEventCreateWithFlags(&s_evJ, cudaEventDisableTiming);
        cudaEventCreateWithFlags(&s_evG, cudaEventDisableTiming);
        for (int c = 0; c < NCHUNK; c++)
            cudaEventCreateWithFlags(&s_evA[c], cudaEventDisableTiming);
        s_init = 1;
    }

    const int TB = 256;
    int mblk = (N_NODES + 127) / 128;              // 391

    // ---- fork: side stream runs CSR + BN folding + layer-2 prep under GEMM1 ----
    cudaEventRecord(s_evF, 0);
    cudaStreamWaitEvent(s_side, s_evF, 0);

    deg_zero<<<(N_NODES + TB - 1) / TB, TB, 0, s_side>>>(deg);
    deg_hist<<<(ETOT + TB - 1) / TB, TB, 0, s_side>>>(ei, deg);
    scan_kernel<<<1, 1024, 0, s_side>>>(deg, off, cursor);
    csr_scatter<<<(ETOT + TB - 1) / TB, TB, 0, s_side>>>(ei, cursor, csr_src);
    bn_prep<<<(W1 + 255) / 256, 256, 0, s_side>>>(bias1, bn1g, bn1b, bn1m, bn1v,
                                                  bns1, bnt1, W1);
    bn_prep<<<(W2 + 255) / 256, 256, 0, s_side>>>(bias2, bn2g, bn2b, bn2m, bn2v,
                                                  bns2, bnt2, W2);
    cat2<<<(W2 + 255) / 256, 256, 0, s_side>>>(bl2, br2, bc2, W2);
    cvt_W_pair<<<(2 * K2 * W2 + TB - 1) / TB, TB, 0, s_side>>>(Wl2, Wr2, Wc2, K2, W2);
    cudaEventRecord(s_evJ, s_side);

    // ---- main: layer-1 prep + GEMM1 ----
    cat2<<<(W1 + 255) / 256, 256>>>(bl1, br1, bc1, W1);
    cvt_A<<<(N_NODES * K1 + TB - 1) / TB, TB>>>(x, As1, N_NODES * K1);
    cvt_W_pair<<<(2 * K1 * W1 + TB - 1) / TB, TB>>>(Wl1, Wr1, Wc1, K1, W1);
    {
        dim3 g1((2 * W1) / 128, mblk);
        gemm_mma<<<g1, 256, 3 * STAGE_BYTES>>>(As1, Wc1, bc1, xl1h, xr1h,
                                               N_NODES, K1, 2 * W1, W1, 0);
    }

    // ---- join side prep ----
    cudaStreamWaitEvent(0, s_evJ, 0);

    // ---- pipelined agg1 -> GEMM2 in NCHUNK M-chunks (2 warps/node) ----
    {
        int blk_per = (mblk + NCHUNK - 1) / NCHUNK;
        for (int c = 0; c < NCHUNK; c++) {
            int b0 = c * blk_per;
            int b1 = min(b0 + blk_per, mblk);
            if (b0 >= b1) break;
            int n0 = b0 * 128;
            int n1 = min(b1 * 128, N_NODES);
            int nwarp = (n1 - n0) * 2;   // 2 head-groups per node
            fused_agg<H1, 2><<<(nwarp * 32 + TB - 1) / TB, TB>>>(
                xl1h, xr1h, att1, off, csr_src, bns1, bnt1, As2, n0, n1);
            cudaEventRecord(s_evA[c], 0);
            cudaStreamWaitEvent(s_side, s_evA[c], 0);
            dim3 g2((2 * W2) / 128, b1 - b0);
            gemm_mma<<<g2, 256, 3 * STAGE_BYTES, s_side>>>(
                As2, Wc2, bc2, xl2h, xr2h, N_NODES, K2, 2 * W2, W2, b0);
        }
        cudaEventRecord(s_evG, s_side);
        cudaStreamWaitEvent(0, s_evG, 0);
    }

    // ---- layer-2 aggregation (2 warps/node) + head ----
    {
        int nwarp = N_NODES * 2;
        fused_agg<H2, 1><<<(nwarp * 32 + TB - 1) / TB, TB>>>(
            xl2h, xr2h, att2, off, csr_src, bns2, bnt2, zh, 0, N_NODES);
    }
    head_kernel<<<(N_PRED * 32 + TB - 1) / TB, TB>>>(zh, pe, pr, pert, Wp, bp, out);
}

// round 17
// speedup vs baseline: 1.0873x; 1.0873x over previous
#include <cuda_runtime.h>
#include <cuda_fp16.h>
#include <math.h>
#include <cstdint>

// ---------------- problem constants ----------------
#define N_NODES 50000
#define N_EDGES 600000
#define N_PRED  200000
#define ETOT    (N_EDGES + N_NODES)
#define W1      512
#define W2      256
#define H1      4
#define H2      2
#define K1      128
#define K2      512
#define BN_EPS  1e-5f
#define NCHUNK  4

// ---------------- scratch (device globals) ----------------
__device__ __half g_xl1h[(size_t)N_NODES * W1];
__device__ __half g_xr1h[(size_t)N_NODES * W1];
__device__ __half g_xl2h[(size_t)N_NODES * W2];
__device__ __half g_xr2h[(size_t)N_NODES * W2];
__device__ __half g_zh [(size_t)N_NODES * W2];

__device__ __half g_As1[(size_t)N_NODES * K1];
__device__ __half g_As2[(size_t)N_NODES * K2];
__device__ __half g_Wc1[(2 * W1) * K1];
__device__ __half g_Wc2[(2 * W2) * K2];

__device__ float g_bc1[2 * W1];
__device__ float g_bc2[2 * W2];

__device__ int g_deg[N_NODES];
__device__ int g_off[N_NODES + 1];
__device__ int g_cursor[N_NODES];
__device__ int g_csr_src[ETOT];

__device__ float g_bns1[W1];
__device__ float g_bnt1[W1];
__device__ float g_bns2[W2];
__device__ float g_bnt2[W2];

// ---------------- helpers ----------------
__device__ __forceinline__ uint32_t smem_to_u32(const void* p) {
    uint32_t a;
    asm("{ .reg .u64 t; cvta.to.shared.u64 t, %1; cvt.u32.u64 %0, t; }" : "=r"(a) : "l"(p));
    return a;
}
#define SWZ128(b) ((b) ^ (((b) >> 3) & 0x70))

__device__ __forceinline__ void ldmatrix_x4(uint32_t* r, uint32_t addr) {
    asm volatile("ldmatrix.sync.aligned.m8n8.x4.shared.b16 {%0,%1,%2,%3}, [%4];"
                 : "=r"(r[0]), "=r"(r[1]), "=r"(r[2]), "=r"(r[3]) : "r"(addr));
}
__device__ __forceinline__ void mma16816h(float* c, const uint32_t* a,
                                          uint32_t b0, uint32_t b1) {
    asm volatile("mma.sync.aligned.m16n8k16.row.col.f32.f16.f16.f32 "
                 "{%0,%1,%2,%3}, {%4,%5,%6,%7}, {%8,%9}, {%0,%1,%2,%3};"
                 : "+f"(c[0]), "+f"(c[1]), "+f"(c[2]), "+f"(c[3])
                 : "r"(a[0]), "r"(a[1]), "r"(a[2]), "r"(a[3]), "r"(b0), "r"(b1));
}
__device__ __forceinline__ float4 h4_to_f4(uint2 u) {
    float2 lo = __half22float2(*(__half2*)&u.x);
    float2 hi = __half22float2(*(__half2*)&u.y);
    return make_float4(lo.x, lo.y, hi.x, hi.y);
}

// ---------------- prep kernels ----------------
__global__ void cvt_A(const float* __restrict__ X, __half* __restrict__ out, int n) {
    int idx = blockIdx.x * blockDim.x + threadIdx.x;
    if (idx < n) out[idx] = __float2half(X[idx]);
}

__global__ void cvt_W_pair(const float* __restrict__ Wl, const float* __restrict__ Wr,
                           __half* __restrict__ out, int K, int Nn) {
    int idx = blockIdx.x * blockDim.x + threadIdx.x;
    if (idx >= 2 * K * Nn) return;
    const float* W = (idx < K * Nn) ? Wl : Wr;
    int rem = (idx < K * Nn) ? idx : idx - K * Nn;
    int noff = (idx < K * Nn) ? 0 : Nn;
    int k = rem / Nn, n = rem - k * Nn;
    out[(size_t)(n + noff) * K + k] = __float2half(W[rem]);
}

__global__ void cat2(const float* __restrict__ a, const float* __restrict__ b,
                     float* __restrict__ o, int n) {
    int i = blockIdx.x * blockDim.x + threadIdx.x;
    if (i < n) { o[i] = a[i]; o[n + i] = b[i]; }
}

// ---------------- HMMA fp16 GEMM ----------------
#define STAGE_BYTES 32768   // 16KB A + 16KB B

__global__ __launch_bounds__(256, 2)
void gemm_mma(const __half* __restrict__ A, const __half* __restrict__ B,
              const float* __restrict__ bias, __half* __restrict__ Cl,
              __half* __restrict__ Cr,
              int M, int Ks, int Nn, int Wn, int moff) {
    extern __shared__ __align__(1024) char sm[];
    int tid = threadIdx.x;
    int wid = tid >> 5, lane = tid & 31;
    int m0 = (blockIdx.y + moff) * 128, n0 = blockIdx.x * 128;
    int wm = wid >> 1, wn = wid & 1;
    uint32_t smb = smem_to_u32(sm);

    float acc[2][8][4];
#pragma unroll
    for (int t = 0; t < 2; t++)
#pragma unroll
        for (int j = 0; j < 8; j++)
#pragma unroll
            for (int q = 0; q < 4; q++) acc[t][j][q] = 0.f;

    int nch = Ks / 64;

    auto issue_load = [&](int c, int s) {
        uint32_t base = smb + s * STAGE_BYTES;
#pragma unroll
        for (int r = 0; r < 4; r++) {
            int idx = tid + r * 256;
            int row = idx >> 3, j = idx & 7;
            const __half* gp = A + (size_t)(m0 + row) * Ks + c * 64 + j * 8;
            uint32_t sa = base + SWZ128(row * 128 + j * 16);
            int sz = (m0 + row < M) ? 16 : 0;
            asm volatile("cp.async.cg.shared.global [%0], [%1], 16, %2;"
                         :: "r"(sa), "l"(gp), "r"(sz));
        }
#pragma unroll
        for (int r = 0; r < 4; r++) {
            int idx = tid + r * 256;
            int row = idx >> 3, j = idx & 7;
            const __half* gp = B + (size_t)(n0 + row) * Ks + c * 64 + j * 8;
            uint32_t sa = base + 16384 + SWZ128(row * 128 + j * 16);
            asm volatile("cp.async.cg.shared.global [%0], [%1], 16;"
                         :: "r"(sa), "l"(gp));
        }
        asm volatile("cp.async.commit_group;");
    };

    issue_load(0, 0);
    if (nch > 1) issue_load(1, 1);

    for (int c = 0; c < nch; c++) {
        if (c + 1 < nch) asm volatile("cp.async.wait_group 1;");
        else             asm volatile("cp.async.wait_group 0;");
        __syncthreads();
        if (c + 2 < nch) issue_load(c + 2, (c + 2) % 3);

        uint32_t ab = smb + (c % 3) * STAGE_BYTES;
        uint32_t bb = ab + 16384;
#pragma unroll
        for (int kk = 0; kk < 4; kk++) {
            uint32_t af[2][4];
#pragma unroll
            for (int t = 0; t < 2; t++) {
                int rl = 32 * wm + 16 * t + (lane & 15);
                uint32_t ad = ab + SWZ128(rl * 128 + kk * 32 + (lane >> 4) * 16);
                ldmatrix_x4(af[t], ad);
            }
            uint32_t bf[4][4];
#pragma unroll
            for (int p = 0; p < 4; p++) {
                int nl = 64 * wn + 16 * p + ((lane >> 4) << 3) + (lane & 7);
                uint32_t bd = bb + SWZ128(nl * 128 + kk * 32 + ((lane >> 3) & 1) * 16);
                ldmatrix_x4(bf[p], bd);
            }
#pragma unroll
            for (int t = 0; t < 2; t++)
#pragma unroll
                for (int j = 0; j < 8; j++)
                    mma16816h(acc[t][j], af[t],
                              bf[j >> 1][(j & 1) * 2], bf[j >> 1][(j & 1) * 2 + 1]);
        }
    }

    int cbase = n0 + 64 * wn;
    bool isL = (cbase < Wn);
    int coff = isL ? cbase : cbase - Wn;
    __half* Cd = isL ? Cl : Cr;
#pragma unroll
    for (int t = 0; t < 2; t++) {
        int gr = m0 + 32 * wm + 16 * t + (lane >> 2);
#pragma unroll
        for (int j = 0; j < 8; j++) {
            int gc = coff + 8 * j + (lane & 3) * 2;
            float2 bi = *(const float2*)(bias + cbase + 8 * j + (lane & 3) * 2);
            if (gr < M)
                *(__half2*)(Cd + (size_t)gr * Wn + gc) =
                    __floats2half2_rn(acc[t][j][0] + bi.x, acc[t][j][1] + bi.y);
            if (gr + 8 < M)
                *(__half2*)(Cd + (size_t)(gr + 8) * Wn + gc) =
                    __floats2half2_rn(acc[t][j][2] + bi.x, acc[t][j][3] + bi.y);
        }
    }
}

// ---------------- BN prep ----------------
__global__ void bn_prep(const float* __restrict__ bias, const float* __restrict__ g,
                        const float* __restrict__ b, const float* __restrict__ m,
                        const float* __restrict__ v, float* __restrict__ s,
                        float* __restrict__ t, int n) {
    int i = blockIdx.x * blockDim.x + threadIdx.x;
    if (i < n) {
        float sc = g[i] * rsqrtf(v[i] + BN_EPS);
        s[i] = sc;
        t[i] = b[i] + (bias[i] - m[i]) * sc;
    }
}

// ---------------- CSR build ----------------
__global__ void deg_zero(int* deg) {
    int i = blockIdx.x * blockDim.x + threadIdx.x;
    if (i < N_NODES) deg[i] = 0;
}
__global__ void deg_hist(const int* __restrict__ ei, int* __restrict__ deg) {
    int i = blockIdx.x * blockDim.x + threadIdx.x;
    if (i >= ETOT) return;
    int dst = (i < N_EDGES) ? ei[N_EDGES + i] : (i - N_EDGES);
    atomicAdd(&deg[dst], 1);
}
__global__ void scan_kernel(const int* __restrict__ deg, int* __restrict__ off,
                            int* __restrict__ cursor) {
    __shared__ int warp_sums[32];
    const int T = 1024;
    int tid = threadIdx.x;
    int chunk = (N_NODES + T - 1) / T;
    int start = tid * chunk;
    int end = min(start + chunk, N_NODES);
    int local = 0;
    for (int i = start; i < end; i++) local += deg[i];
    int lane = tid & 31, wid = tid >> 5;
    int v = local;
#pragma unroll
    for (int o = 1; o < 32; o <<= 1) {
        int u = __shfl_up_sync(0xFFFFFFFFu, v, o);
        if (lane >= o) v += u;
    }
    if (lane == 31) warp_sums[wid] = v;
    __syncthreads();
    if (wid == 0) {
        int s = warp_sums[lane];
#pragma unroll
        for (int o = 1; o < 32; o <<= 1) {
            int u = __shfl_up_sync(0xFFFFFFFFu, s, o);
            if (lane >= o) s += u;
        }
        warp_sums[lane] = s;
    }
    __syncthreads();
    int excl = v - local + (wid > 0 ? warp_sums[wid - 1] : 0);
    int run = excl;
    for (int i = start; i < end; i++) {
        off[i] = run;
        cursor[i] = run;
        run += deg[i];
    }
    if (tid == T - 1) off[N_NODES] = run;
}
__global__ void csr_scatter(const int* __restrict__ ei, int* __restrict__ cursor,
                            int* __restrict__ csr_src) {
    int i = blockIdx.x * blockDim.x + threadIdx.x;
    if (i >= ETOT) return;
    int src, dst;
    if (i < N_EDGES) { src = ei[i]; dst = ei[N_EDGES + i]; }
    else             { src = dst = i - N_EDGES; }
    int pos = atomicAdd(&cursor[dst], 1);
    csr_src[pos] = src;
}

// ---------------- fused GATv2 aggregation, batch-2 online softmax --------------
// One warp per node, all H heads (round-15 mapping).
template<int H>
__global__ __launch_bounds__(256)
void fused_agg(const __half* __restrict__ xl, const __half* __restrict__ xr,
               const float* __restrict__ att,
               const int* __restrict__ off, const int* __restrict__ csr_src,
               const float* __restrict__ bns, const float* __restrict__ bnt,
               __half* __restrict__ outp, int node0, int node1) {
    int node = node0 + ((blockIdx.x * blockDim.x + threadIdx.x) >> 5);
    int lane = threadIdx.x & 31;
    if (node >= node1) return;
    const int Wd = H * 128;

    const uint2* xr4 = (const uint2*)(xr + (size_t)node * Wd);
    const float4* at4 = (const float4*)att;

    float4 xrr[H], attr[H], acc[H];
    float m[H], sum[H];
#pragma unroll
    for (int h = 0; h < H; h++) {
        xrr[h]  = h4_to_f4(xr4[h * 32 + lane]);
        attr[h] = at4[h * 32 + lane];
        acc[h]  = make_float4(0.f, 0.f, 0.f, 0.f);
        m[h]    = -INFINITY;
        sum[h]  = 0.f;
    }

    auto loadrow = [&](int src, float4* v) {
        const uint2* p = (const uint2*)(xl + (size_t)src * Wd);
#pragma unroll
        for (int h = 0; h < H; h++) v[h] = h4_to_f4(p[h * 32 + lane]);
    };

    int e0 = off[node], e1 = off[node + 1];
    for (int e = e0; e < e1; e += 2) {
        int nb = e1 - e;
        int s0 = csr_src[e];
        int s1 = (nb > 1) ? csr_src[e + 1] : s0;

        float4 v0[H], v1[H];
        loadrow(s0, v0);
        loadrow(s1, v1);

        float sc0[H], sc1[H];
#pragma unroll
        for (int h = 0; h < H; h++) {
            float ex = v0[h].x + xrr[h].x; ex = ex > 0.f ? ex : 0.2f * ex;
            float ey = v0[h].y + xrr[h].y; ey = ey > 0.f ? ey : 0.2f * ey;
            float ez = v0[h].z + xrr[h].z; ez = ez > 0.f ? ez : 0.2f * ez;
            float ew = v0[h].w + xrr[h].w; ew = ew > 0.f ? ew : 0.2f * ew;
            sc0[h] = ex * attr[h].x + ey * attr[h].y + ez * attr[h].z + ew * attr[h].w;
            ex = v1[h].x + xrr[h].x; ex = ex > 0.f ? ex : 0.2f * ex;
            ey = v1[h].y + xrr[h].y; ey = ey > 0.f ? ey : 0.2f * ey;
            ez = v1[h].z + xrr[h].z; ez = ez > 0.f ? ez : 0.2f * ez;
            ew = v1[h].w + xrr[h].w; ew = ew > 0.f ? ew : 0.2f * ew;
            sc1[h] = ex * attr[h].x + ey * attr[h].y + ez * attr[h].z + ew * attr[h].w;
        }
#pragma unroll
        for (int o = 16; o > 0; o >>= 1)
#pragma unroll
            for (int h = 0; h < H; h++) {
                sc0[h] += __shfl_xor_sync(0xFFFFFFFFu, sc0[h], o);
                sc1[h] += __shfl_xor_sync(0xFFFFFFFFu, sc1[h], o);
            }
        if (nb < 2)
#pragma unroll
            for (int h = 0; h < H; h++) sc1[h] = -INFINITY;

#pragma unroll
        for (int h = 0; h < H; h++) {
            float sb = fmaxf(sc0[h], sc1[h]);
            float mn = fmaxf(m[h], sb);
            float c  = __expf(m[h] - mn);
            float p0 = __expf(sc0[h] - mn);
            float p1 = __expf(sc1[h] - mn);
            sum[h] = sum[h] * c + p0 + p1;
            acc[h].x = acc[h].x * c + p0 * v0[h].x + p1 * v1[h].x;
            acc[h].y = acc[h].y * c + p0 * v0[h].y + p1 * v1[h].y;
            acc[h].z = acc[h].z * c + p0 * v0[h].z + p1 * v1[h].z;
            acc[h].w = acc[h].w * c + p0 * v0[h].w + p1 * v1[h].w;
            m[h] = mn;
        }
    }

#pragma unroll
    for (int h = 0; h < H; h++) {
        int cbase = h * 128 + lane * 4;
        float4 sc4 = *(const float4*)(bns + cbase);
        float4 tt = *(const float4*)(bnt + cbase);
        float inv = 1.f / sum[h];
        float4 o;
        o.x = fmaxf(fmaf(acc[h].x * inv, sc4.x, tt.x), 0.f);
        o.y = fmaxf(fmaf(acc[h].y * inv, sc4.y, tt.y), 0.f);
        o.z = fmaxf(fmaf(acc[h].z * inv, sc4.z, tt.z), 0.f);
        o.w = fmaxf(fmaf(acc[h].w * inv, sc4.w, tt.w), 0.f);
        __half2 ha = __floats2half2_rn(o.x, o.y);
        __half2 hb = __floats2half2_rn(o.z, o.w);
        uint2 pk;
        pk.x = *(uint32_t*)&ha;
        pk.y = *(uint32_t*)&hb;
        *(uint2*)(outp + (size_t)node * Wd + cbase) = pk;
    }
}

// ---------------- prediction head: 2 pred edges per warp ----------------
__global__ void head_kernel(const __half* __restrict__ z, const int* __restrict__ pe,
                            const float* __restrict__ pr, const float* __restrict__ pert,
                            const float* __restrict__ Wp, const float* __restrict__ bp,
                            float* __restrict__ out) {
    __shared__ float sw[(W2 * 2 + 3) * 2];
    for (int i = threadIdx.x; i < (W2 * 2 + 3) * 2; i += blockDim.x) sw[i] = Wp[i];
    __syncthreads();

    int w = (blockIdx.x * blockDim.x + threadIdx.x) >> 5;   // handles edges 2w, 2w+1
    int lane = threadIdx.x & 31;
    int eA = 2 * w, eB = 2 * w + 1;
    if (eA >= N_PRED) return;
    int sA = pe[eA], dA = pe[N_PRED + eA];
    int sB = pe[eB], dB = pe[N_PRED + eB];   // N_PRED even -> eB always valid

    const uint2* zsA = (const uint2*)(z + (size_t)sA * W2);
    const uint2* zdA = (const uint2*)(z + (size_t)dA * W2);
    const uint2* zsB = (const uint2*)(z + (size_t)sB * W2);
    const uint2* zdB = (const uint2*)(z + (size_t)dB * W2);

    float a0A = 0.f, a1A = 0.f, a0B = 0.f, a1B = 0.f;
#pragma unroll
    for (int q = 0; q < 2; q++) {
        int r = lane * 2 + q;
        int base = (r * 4) * 2;
        int base2 = (W2 + r * 4) * 2;
        float4 v;
        v = h4_to_f4(zsA[r]);
        a0A += v.x * sw[base] + v.y * sw[base + 2] + v.z * sw[base + 4] + v.w * sw[base + 6];
        a1A += v.x * sw[base + 1] + v.y * sw[base + 3] + v.z * sw[base + 5] + v.w * sw[base + 7];
        v = h4_to_f4(zdA[r]);
        a0A += v.x * sw[base2] + v.y * sw[base2 + 2] + v.z * sw[base2 + 4] + v.w * sw[base2 + 6];
        a1A += v.x * sw[base2 + 1] + v.y * sw[base2 + 3] + v.z * sw[base2 + 5] + v.w * sw[base2 + 7];
        v = h4_to_f4(zsB[r]);
        a0B += v.x * sw[base] + v.y * sw[base + 2] + v.z * sw[base + 4] + v.w * sw[base + 6];
        a1B += v.x * sw[base + 1] + v.y * sw[base + 3] + v.z * sw[base + 5] + v.w * sw[base + 7];
        v = h4_to_f4(zdB[r]);
        a0B += v.x * sw[base2] + v.y * sw[base2 + 2] + v.z * sw[base2 + 4] + v.w * sw[base2 + 6];
        a1B += v.x * sw[base2 + 1] + v.y * sw[base2 + 3] + v.z * sw[base2 + 5] + v.w * sw[base2 + 7];
    }
    if (lane == 0) {
        int b0 = (2 * W2) * 2;
        float prsA = pr[sA], prdA = pr[dA], ppA = pert[sA] * pert[dA];
        a0A += prsA * sw[b0] + prdA * sw[b0 + 2] + ppA * sw[b0 + 4];
        a1A += prsA * sw[b0 + 1] + prdA * sw[b0 + 3] + ppA * sw[b0 + 5];
        float prsB = pr[sB], prdB = pr[dB], ppB = pert[sB] * pert[dB];
        a0B += prsB * sw[b0] + prdB * sw[b0 + 2] + ppB * sw[b0 + 4];
        a1B += prsB * sw[b0 + 1] + prdB * sw[b0 + 3] + ppB * sw[b0 + 5];
    }
#pragma unroll
    for (int o = 16; o > 0; o >>= 1) {
        a0A += __shfl_xor_sync(0xFFFFFFFFu, a0A, o);
        a1A += __shfl_xor_sync(0xFFFFFFFFu, a1A, o);
        a0B += __shfl_xor_sync(0xFFFFFFFFu, a0B, o);
        a1B += __shfl_xor_sync(0xFFFFFFFFu, a1B, o);
    }
    if (lane == 0) {
        out[(size_t)eA * 2 + 0] = a0A + bp[0];
        out[(size_t)eA * 2 + 1] = a1A + bp[1];
        out[(size_t)eB * 2 + 0] = a0B + bp[0];
        out[(size_t)eB * 2 + 1] = a1B + bp[1];
    }
}

// ---------------- launch ----------------
extern "C" void kernel_launch(void* const* d_in, const int* in_sizes, int n_in,
                              void* d_out, int out_size) {
    const float* x     = (const float*)d_in[0];
    const int*   ei    = (const int*)d_in[1];
    const int*   pe    = (const int*)d_in[2];
    const float* pert  = (const float*)d_in[3];
    const float* pr    = (const float*)d_in[4];
    const float* Wl1   = (const float*)d_in[5];
    const float* bl1   = (const float*)d_in[6];
    const float* Wr1   = (const float*)d_in[7];
    const float* br1   = (const float*)d_in[8];
    const float* att1  = (const float*)d_in[9];
    const float* bias1 = (const float*)d_in[10];
    const float* bn1g  = (const float*)d_in[11];
    const float* bn1b  = (const float*)d_in[12];
    const float* bn1m  = (const float*)d_in[13];
    const float* bn1v  = (const float*)d_in[14];
    const float* Wl2   = (const float*)d_in[15];
    const float* bl2   = (const float*)d_in[16];
    const float* Wr2   = (const float*)d_in[17];
    const float* br2   = (const float*)d_in[18];
    const float* att2  = (const float*)d_in[19];
    const float* bias2 = (const float*)d_in[20];
    const float* bn2g  = (const float*)d_in[21];
    const float* bn2b  = (const float*)d_in[22];
    const float* bn2m  = (const float*)d_in[23];
    const float* bn2v  = (const float*)d_in[24];
    const float* Wp    = (const float*)d_in[25];
    const float* bp    = (const float*)d_in[26];
    float* out = (float*)d_out;

    __half *xl1h, *xr1h, *xl2h, *xr2h, *zh, *As1, *As2, *Wc1, *Wc2;
    float *bc1, *bc2, *bns1, *bnt1, *bns2, *bnt2;
    int *deg, *off, *cursor, *csr_src;
    cudaGetSymbolAddress((void**)&xl1h, g_xl1h);
    cudaGetSymbolAddress((void**)&xr1h, g_xr1h);
    cudaGetSymbolAddress((void**)&xl2h, g_xl2h);
    cudaGetSymbolAddress((void**)&xr2h, g_xr2h);
    cudaGetSymbolAddress((void**)&zh,  g_zh);
    cudaGetSymbolAddress((void**)&bc1, g_bc1);
    cudaGetSymbolAddress((void**)&bc2, g_bc2);
    cudaGetSymbolAddress((void**)&bns1, g_bns1);
    cudaGetSymbolAddress((void**)&bnt1, g_bnt1);
    cudaGetSymbolAddress((void**)&bns2, g_bns2);
    cudaGetSymbolAddress((void**)&bnt2, g_bnt2);
    cudaGetSymbolAddress((void**)&deg, g_deg);
    cudaGetSymbolAddress((void**)&off, g_off);
    cudaGetSymbolAddress((void**)&cursor, g_cursor);
    cudaGetSymbolAddress((void**)&csr_src, g_csr_src);
    cudaGetSymbolAddress((void**)&As1, g_As1);
    cudaGetSymbolAddress((void**)&As2, g_As2);
    cudaGetSymbolAddress((void**)&Wc1, g_Wc1);
    cudaGetSymbolAddress((void**)&Wc2, g_Wc2);

    static int s_init = 0;
    static cudaStream_t s_side;
    static cudaEvent_t s_evF, s_evJ, s_evA[NCHUNK], s_evG;
    if (!s_init) {
        cudaFuncSetAttribute(gemm_mma, cudaFuncAttributeMaxDynamicSharedMemorySize,
                             3 * STAGE_BYTES);
        cudaStreamCreateWithFlags(&s_side, cudaStreamNonBlocking);
        cudaEventCreateWithFlags(&s_evF, cudaEventDisableTiming);
        cudaEventCreateWithFlags(&s_evJ, cudaEventDisableTiming);
        cudaEventCreateWithFlags(&s_evG, cudaEventDisableTiming);
        for (int c = 0; c < NCHUNK; c++)
            cudaEventCreateWithFlags(&s_evA[c], cudaEventDisableTiming);
        s_init = 1;
    }

    const int TB = 256;
    int mblk = (N_NODES + 127) / 128;              // 391

    // ---- fork: side stream. Early join covers ONLY CSR + bns1 (agg1 deps);
    //      layer-2 prep continues on side behind it (covered by evG). ----
    cudaEventRecord(s_evF, 0);
    cudaStreamWaitEvent(s_side, s_evF, 0);

    deg_zero<<<(N_NODES + TB - 1) / TB, TB, 0, s_side>>>(deg);
    deg_hist<<<(ETOT + TB - 1) / TB, TB, 0, s_side>>>(ei, deg);
    scan_kernel<<<1, 1024, 0, s_side>>>(deg, off, cursor);
    csr_scatter<<<(ETOT + TB - 1) / TB, TB, 0, s_side>>>(ei, cursor, csr_src);
    bn_prep<<<(W1 + 255) / 256, 256, 0, s_side>>>(bias1, bn1g, bn1b, bn1m, bn1v,
                                                  bns1, bnt1, W1);
    cudaEventRecord(s_evJ, s_side);
    // layer-2 prep (needed by GEMM2 on side / agg2 after evG)
    bn_prep<<<(W2 + 255) / 256, 256, 0, s_side>>>(bias2, bn2g, bn2b, bn2m, bn2v,
                                                  bns2, bnt2, W2);
    cat2<<<(W2 + 255) / 256, 256, 0, s_side>>>(bl2, br2, bc2, W2);
    cvt_W_pair<<<(2 * K2 * W2 + TB - 1) / TB, TB, 0, s_side>>>(Wl2, Wr2, Wc2, K2, W2);

    // ---- main: layer-1 prep + GEMM1 ----
    cat2<<<(W1 + 255) / 256, 256>>>(bl1, br1, bc1, W1);
    cvt_A<<<(N_NODES * K1 + TB - 1) / TB, TB>>>(x, As1, N_NODES * K1);
    cvt_W_pair<<<(2 * K1 * W1 + TB - 1) / TB, TB>>>(Wl1, Wr1, Wc1, K1, W1);
    {
        dim3 g1((2 * W1) / 128, mblk);
        gemm_mma<<<g1, 256, 3 * STAGE_BYTES>>>(As1, Wc1, bc1, xl1h, xr1h,
                                               N_NODES, K1, 2 * W1, W1, 0);
    }

    // ---- join CSR + bns1 ----
    cudaStreamWaitEvent(0, s_evJ, 0);

    // ---- pipelined agg1 -> GEMM2 in NCHUNK M-chunks ----
    {
        int blk_per = (mblk + NCHUNK - 1) / NCHUNK;
        for (int c = 0; c < NCHUNK; c++) {
            int b0 = c * blk_per;
            int b1 = min(b0 + blk_per, mblk);
            if (b0 >= b1) break;
            int n0 = b0 * 128;
            int n1 = min(b1 * 128, N_NODES);
            int nwarp = n1 - n0;
            fused_agg<H1><<<(nwarp * 32 + TB - 1) / TB, TB>>>(
                xl1h, xr1h, att1, off, csr_src, bns1, bnt1, As2, n0, n1);
            cudaEventRecord(s_evA[c], 0);
            cudaStreamWaitEvent(s_side, s_evA[c], 0);
            dim3 g2((2 * W2) / 128, b1 - b0);
            gemm_mma<<<g2, 256, 3 * STAGE_BYTES, s_side>>>(
                As2, Wc2, bc2, xl2h, xr2h, N_NODES, K2, 2 * W2, W2, b0);
        }
        cudaEventRecord(s_evG, s_side);
        cudaStreamWaitEvent(0, s_evG, 0);
    }

    // ---- layer-2 aggregation + head ----
    {
        int nwarp_blk = (N_NODES * 32 + TB - 1) / TB;
        fused_agg<H2><<<nwarp_blk, TB>>>(xl2h, xr2h, att2,
                                         off, csr_src, bns2, bnt2, zh,
                                         0, N_NODES);
    }
    head_kernel<<<((N_PRED / 2) * 32 + TB - 1) / TB, TB>>>(zh, pe, pr, pert, Wp, bp, out);
}